// round 9
// baseline (speedup 1.0000x reference)
#include <cuda_runtime.h>
#include <cstdint>
#include <cstddef>

#define N_NODES 100000
#define N_EDGES 1280000
#define D 64

typedef unsigned long long u64;

// Packed fp32x2 FMA (Blackwell). Packs over adjacent K indices; operands come
// straight out of LDS.128 register pairs. lo+hi folded with one FADD at the end.
#define FMA2(acc, a, b) \
    asm("fma.rn.f32x2 %0, %1, %2, %0;" : "+l"(acc) : "l"(a), "l"(b))

union F2U { u64 u; float2 f; };

// Scratch (all static __device__ — no allocations):
__device__ float4 g_S[(size_t)N_NODES * 32];   // [node][fwd64|rev64] as float4
__device__ int g_deg[N_NODES];                  // histogram
__device__ int g_off[N_NODES + 1];              // CSR offsets
__device__ int g_cur[N_NODES];                  // fill cursors
__device__ int g_eid[N_EDGES];                  // dst-sorted edge ids

// ---------------------------------------------------------------------------
// S0: zero the dst histogram
// ---------------------------------------------------------------------------
__global__ void k_init() {
    int i = blockIdx.x * blockDim.x + threadIdx.x;
    if (i < N_NODES) g_deg[i] = 0;
}

// ---------------------------------------------------------------------------
// S1: histogram of dst
// ---------------------------------------------------------------------------
__global__ void k_hist(const int* __restrict__ dst) {
    int e = blockIdx.x * blockDim.x + threadIdx.x;
    if (e < N_EDGES) atomicAdd(&g_deg[dst[e]], 1);
}

// ---------------------------------------------------------------------------
// S2: single-block exclusive prefix scan of g_deg -> g_off, g_cur
// 1024 threads, each owns a contiguous chunk of 98 nodes.
// ---------------------------------------------------------------------------
__global__ __launch_bounds__(1024) void k_scan() {
    __shared__ int part[1024];
    const int CH = 98;                      // 1024*98 >= 100000
    int t = threadIdx.x;
    int base = t * CH;

    int s = 0;
    for (int j = 0; j < CH; j++) {
        int i = base + j;
        if (i < N_NODES) s += g_deg[i];
    }
    part[t] = s;
    __syncthreads();

    // Hillis-Steele inclusive scan
    for (int d = 1; d < 1024; d <<= 1) {
        int v = (t >= d) ? part[t - d] : 0;
        __syncthreads();
        part[t] += v;
        __syncthreads();
    }

    int run = (t == 0) ? 0 : part[t - 1];   // exclusive prefix for this chunk
    for (int j = 0; j < CH; j++) {
        int i = base + j;
        if (i < N_NODES) {
            g_off[i] = run;
            g_cur[i] = run;
            run += g_deg[i];
        }
    }
    if (t == 1023) g_off[N_NODES] = part[1023];
}

// ---------------------------------------------------------------------------
// S3: build dst-sorted permutation
// ---------------------------------------------------------------------------
__global__ void k_perm(const int* __restrict__ dst) {
    int e = blockIdx.x * blockDim.x + threadIdx.x;
    if (e < N_EDGES) {
        int pos = atomicAdd(&g_cur[dst[e]], 1);
        g_eid[pos] = e;
    }
}

// ---------------------------------------------------------------------------
// S4: gather-reduce aggregation, one warp per node, NO fp atomics.
// lane l owns channels [2l, 2l+1]. Accumulates fwd/rev in registers,
// writes g_S[node] once (zeros for isolated nodes — replaces k_zero).
// ---------------------------------------------------------------------------
__global__ __launch_bounds__(256) void k_agg(
    const float* __restrict__ node_feat,
    const float* __restrict__ edge_feat,
    const float* __restrict__ edge_norm,
    const int*   __restrict__ src,
    const int*   __restrict__ is_rev)
{
    int warp = (blockIdx.x * blockDim.x + threadIdx.x) >> 5;
    int l = threadIdx.x & 31;
    if (warp >= N_NODES) return;
    int n = warp;

    int beg = g_off[n];
    int end = g_off[n + 1];

    float2 f = make_float2(0.f, 0.f);
    float2 r = make_float2(0.f, 0.f);

    for (int p = beg; p < end; p++) {
        int e  = __ldg(&g_eid[p]);          // broadcast
        int s  = __ldg(&src[e]);
        float nr = __ldg(&edge_norm[e]);
        int rv = __ldg(&is_rev[e]);
        float2 a = *reinterpret_cast<const float2*>(node_feat + (size_t)s * 64 + 2 * l);
        float2 b = *reinterpret_cast<const float2*>(edge_feat + (size_t)e * 64 + 2 * l);
        float mx = a.x * b.x * nr;
        float my = a.y * b.y * nr;
        if (rv) { r.x += mx; r.y += my; }
        else    { f.x += mx; f.y += my; }
    }

    float* o = reinterpret_cast<float*>(g_S) + (size_t)n * 128;
    *reinterpret_cast<float2*>(o + 2 * l)      = f;
    *reinterpret_cast<float2*>(o + 64 + 2 * l) = r;
}

// ---------------------------------------------------------------------------
// S5: edge_out = edge_feat @ rel_weight (64x64, fp32x2, 8x8 reg tile)
// ---------------------------------------------------------------------------
__global__ __launch_bounds__(64) void k_edge_gemm(
    const float* __restrict__ edge_feat,
    const float* __restrict__ rel_w,
    float* __restrict__ edge_out)
{
    __shared__ float Xs[64][68];
    __shared__ float Wt[64][68];

    const int t  = threadIdx.x;
    const int e0 = blockIdx.x * 64;

    #pragma unroll 8
    for (int k = 0; k < 64; k++)
        Wt[t][k] = rel_w[k * 64 + t];

    const float4* Xg = reinterpret_cast<const float4*>(edge_feat) + (size_t)e0 * 16;
    #pragma unroll
    for (int it = 0; it < 16; it++) {
        int idx = it * 64 + t;
        int rr = idx >> 4;
        int kq = idx & 15;
        float4 v = Xg[(size_t)rr * 16 + kq];
        *reinterpret_cast<float4*>(&Xs[rr][kq * 4]) = v;
    }
    __syncthreads();

    const int tx = t & 7;
    const int ty = t >> 3;
    u64 acc[8][8];
    #pragma unroll
    for (int i = 0; i < 8; i++)
        #pragma unroll
        for (int j = 0; j < 8; j++) acc[i][j] = 0ull;

    #pragma unroll 4
    for (int k4 = 0; k4 < 16; k4++) {
        ulonglong2 xv[8], wv[8];
        #pragma unroll
        for (int i = 0; i < 8; i++)
            xv[i] = *reinterpret_cast<const ulonglong2*>(&Xs[ty + 8 * i][k4 * 4]);
        #pragma unroll
        for (int j = 0; j < 8; j++)
            wv[j] = *reinterpret_cast<const ulonglong2*>(&Wt[tx + 8 * j][k4 * 4]);
        #pragma unroll
        for (int i = 0; i < 8; i++)
            #pragma unroll
            for (int j = 0; j < 8; j++)
                FMA2(acc[i][j], xv[i].x, wv[j].x);
        #pragma unroll
        for (int i = 0; i < 8; i++)
            #pragma unroll
            for (int j = 0; j < 8; j++)
                FMA2(acc[i][j], xv[i].y, wv[j].y);
    }

    #pragma unroll
    for (int i = 0; i < 8; i++) {
        float* o = edge_out + (size_t)(e0 + ty + 8 * i) * 64;
        #pragma unroll
        for (int j = 0; j < 8; j++) {
            F2U c; c.u = acc[i][j];
            o[tx + 8 * j] = c.f.x + c.f.y;
        }
    }
}

// ---------------------------------------------------------------------------
// S6: node kernel (unchanged): 3-chunk K=192 GEMM, fp32x2.
// ---------------------------------------------------------------------------
__global__ __launch_bounds__(64) void k_node(
    const float* __restrict__ node_feat,
    const float* __restrict__ in_w,
    const float* __restrict__ out_w,
    const float* __restrict__ loop_w,
    const float* __restrict__ loop_rel,
    const float* __restrict__ bias,
    float* __restrict__ node_out)
{
    __shared__ float Xs[64][68];
    __shared__ float Wt[64][68];

    const int t  = threadIdx.x;
    const int r0 = blockIdx.x * 64;
    const int tx = t & 7;
    const int ty = t >> 3;
    const float* S = reinterpret_cast<const float*>(g_S);

    u64 acc[8][8];
    #pragma unroll
    for (int i = 0; i < 8; i++)
        #pragma unroll
        for (int j = 0; j < 8; j++) acc[i][j] = 0ull;

    #pragma unroll 1
    for (int ch = 0; ch < 3; ch++) {
        if (ch == 2) {
            #pragma unroll 8
            for (int k = 0; k < 64; k++)
                Wt[t][k] = loop_w[k * 64 + t] * loop_rel[k];
        } else {
            const float* W = (ch == 0) ? in_w : out_w;
            #pragma unroll 8
            for (int k = 0; k < 64; k++)
                Wt[t][k] = W[k * 64 + t];
        }

        const float* Xbase;
        size_t pitch, off;
        if (ch == 0)      { Xbase = S;         pitch = 128; off = 0;  }
        else if (ch == 1) { Xbase = S;         pitch = 128; off = 64; }
        else              { Xbase = node_feat; pitch = 64;  off = 0;  }

        #pragma unroll
        for (int it = 0; it < 16; it++) {
            int idx = it * 64 + t;
            int rr = idx >> 4;
            int kq = idx & 15;
            int gr = r0 + rr;
            float4 v = make_float4(0.f, 0.f, 0.f, 0.f);
            if (gr < N_NODES)
                v = *reinterpret_cast<const float4*>(Xbase + (size_t)gr * pitch + off + kq * 4);
            *reinterpret_cast<float4*>(&Xs[rr][kq * 4]) = v;
        }
        __syncthreads();

        #pragma unroll 4
        for (int k4 = 0; k4 < 16; k4++) {
            ulonglong2 xv[8], wv[8];
            #pragma unroll
            for (int i = 0; i < 8; i++)
                xv[i] = *reinterpret_cast<const ulonglong2*>(&Xs[ty + 8 * i][k4 * 4]);
            #pragma unroll
            for (int j = 0; j < 8; j++)
                wv[j] = *reinterpret_cast<const ulonglong2*>(&Wt[tx + 8 * j][k4 * 4]);
            #pragma unroll
            for (int i = 0; i < 8; i++)
                #pragma unroll
                for (int j = 0; j < 8; j++)
                    FMA2(acc[i][j], xv[i].x, wv[j].x);
            #pragma unroll
            for (int i = 0; i < 8; i++)
                #pragma unroll
                for (int j = 0; j < 8; j++)
                    FMA2(acc[i][j], xv[i].y, wv[j].y);
        }
        __syncthreads();
    }

    #pragma unroll
    for (int i = 0; i < 8; i++) {
        int rr = r0 + ty + 8 * i;
        if (rr < N_NODES) {
            float* o = node_out + (size_t)rr * 64;
            #pragma unroll
            for (int j = 0; j < 8; j++) {
                int c = tx + 8 * j;
                F2U cv; cv.u = acc[i][j];
                o[c] = (cv.f.x + cv.f.y) * 0.3333333f + __ldg(&bias[c]);
            }
        }
    }
}

// ---------------------------------------------------------------------------
// kernel_launch — inputs in setup_inputs dict order; is_rev is int32.
// Output: node_out [N,64] then edge_out [E,64], f32.
// ---------------------------------------------------------------------------
extern "C" void kernel_launch(void* const* d_in, const int* in_sizes, int n_in,
                              void* d_out, int out_size)
{
    const float* node_feat = (const float*)d_in[0];
    const float* edge_feat = (const float*)d_in[1];
    const float* edge_norm = (const float*)d_in[2];
    const int*   src       = (const int*)d_in[3];
    const int*   dst       = (const int*)d_in[4];
    const int*   is_rev    = (const int*)d_in[5];
    const float* in_w      = (const float*)d_in[6];
    const float* out_w     = (const float*)d_in[7];
    const float* rel_w     = (const float*)d_in[8];
    const float* loop_w    = (const float*)d_in[9];
    const float* loop_rel  = (const float*)d_in[10];
    const float* bias      = (const float*)d_in[11];

    float* out      = (float*)d_out;
    float* node_out = out;

    int write_edge = (out_size >= (N_NODES + N_EDGES) * D) ? 1 : 0;
    float* edge_out = write_edge ? (out + (size_t)N_NODES * D) : nullptr;

    // Independent edge GEMM first (also varies ncu sample position)
    if (write_edge)
        k_edge_gemm<<<N_EDGES / 64, 64>>>(edge_feat, rel_w, edge_out);

    // CSR build
    k_init<<<(N_NODES + 255) / 256, 256>>>();
    k_hist<<<(N_EDGES + 255) / 256, 256>>>(dst);
    k_scan<<<1, 1024>>>();
    k_perm<<<(N_EDGES + 255) / 256, 256>>>(dst);

    // Gather-reduce aggregation (no fp atomics, writes g_S fully)
    k_agg<<<(N_NODES * 32 + 255) / 256, 256>>>(node_feat, edge_feat, edge_norm,
                                               src, is_rev);

    // Node GEMM + epilogue
    k_node<<<(N_NODES + 63) / 64, 64>>>(node_feat, in_w, out_w,
                                        loop_w, loop_rel, bias, node_out);
}

// round 10
// speedup vs baseline: 1.3348x; 1.3348x over previous
#include <cuda_runtime.h>
#include <cstdint>
#include <cstddef>

#define N_NODES 100000
#define N_EDGES 1280000
#define D 64
#define SCAN_BLK 256
#define N_SCAN_BLKS ((N_NODES + SCAN_BLK - 1) / SCAN_BLK)   // 391

typedef unsigned long long u64;

// Packed fp32x2 FMA (Blackwell). Packs over adjacent K indices; operands come
// straight out of LDS.128 register pairs. lo+hi folded with one FADD at the end.
#define FMA2(acc, a, b) \
    asm("fma.rn.f32x2 %0, %1, %2, %0;" : "+l"(acc) : "l"(a), "l"(b))

union F2U { u64 u; float2 f; };

// Scratch (all static __device__ — no allocations):
__device__ float4 g_S[(size_t)N_NODES * 32];   // [node][fwd64|rev64] as float4
__device__ int g_deg[N_NODES];                  // histogram
__device__ int g_off[N_NODES + 1];              // CSR offsets
__device__ int g_cur[N_NODES];                  // fill cursors
__device__ int g_eid[N_EDGES];                  // dst-sorted edge ids
__device__ int g_blksum[N_SCAN_BLKS];           // per-block degree sums
__device__ int g_blkoff[N_SCAN_BLKS];           // exclusive block offsets

// ---------------------------------------------------------------------------
// S0: zero the dst histogram
// ---------------------------------------------------------------------------
__global__ void k_init() {
    int i = blockIdx.x * blockDim.x + threadIdx.x;
    if (i < N_NODES) g_deg[i] = 0;
}

// ---------------------------------------------------------------------------
// S1: histogram of dst
// ---------------------------------------------------------------------------
__global__ void k_hist(const int* __restrict__ dst) {
    int e = blockIdx.x * blockDim.x + threadIdx.x;
    if (e < N_EDGES) atomicAdd(&g_deg[dst[e]], 1);
}

// ---------------------------------------------------------------------------
// S2a: per-block degree sums (391 blocks x 256 threads, tree reduction)
// ---------------------------------------------------------------------------
__global__ __launch_bounds__(SCAN_BLK) void k_scanA() {
    __shared__ int sh[SCAN_BLK];
    int t = threadIdx.x;
    int i = blockIdx.x * SCAN_BLK + t;
    sh[t] = (i < N_NODES) ? g_deg[i] : 0;
    __syncthreads();
    #pragma unroll
    for (int d = SCAN_BLK / 2; d > 0; d >>= 1) {
        if (t < d) sh[t] += sh[t + d];
        __syncthreads();
    }
    if (t == 0) g_blksum[blockIdx.x] = sh[0];
}

// ---------------------------------------------------------------------------
// S2b: scan the 391 block sums (single tiny block)
// ---------------------------------------------------------------------------
__global__ __launch_bounds__(512) void k_scanB() {
    __shared__ int sh[512];
    int t = threadIdx.x;
    int v = (t < N_SCAN_BLKS) ? g_blksum[t] : 0;
    sh[t] = v;
    __syncthreads();
    for (int d = 1; d < 512; d <<= 1) {
        int x = (t >= d) ? sh[t - d] : 0;
        __syncthreads();
        sh[t] += x;
        __syncthreads();
    }
    if (t < N_SCAN_BLKS) g_blkoff[t] = sh[t] - v;   // exclusive
    if (t == 511) g_off[N_NODES] = sh[511];         // total (padded zeros)
}

// ---------------------------------------------------------------------------
// S2c: intra-block scan + block offset -> g_off, g_cur
// ---------------------------------------------------------------------------
__global__ __launch_bounds__(SCAN_BLK) void k_scanC() {
    __shared__ int sh[SCAN_BLK];
    int t = threadIdx.x;
    int i = blockIdx.x * SCAN_BLK + t;
    int v = (i < N_NODES) ? g_deg[i] : 0;
    sh[t] = v;
    __syncthreads();
    for (int d = 1; d < SCAN_BLK; d <<= 1) {
        int x = (t >= d) ? sh[t - d] : 0;
        __syncthreads();
        sh[t] += x;
        __syncthreads();
    }
    if (i < N_NODES) {
        int excl = sh[t] - v + g_blkoff[blockIdx.x];
        g_off[i] = excl;
        g_cur[i] = excl;
    }
}

// ---------------------------------------------------------------------------
// S3: build dst-sorted permutation
// ---------------------------------------------------------------------------
__global__ void k_perm(const int* __restrict__ dst) {
    int e = blockIdx.x * blockDim.x + threadIdx.x;
    if (e < N_EDGES) {
        int pos = atomicAdd(&g_cur[dst[e]], 1);
        g_eid[pos] = e;
    }
}

// ---------------------------------------------------------------------------
// S4: gather-reduce aggregation, one warp per node, NO fp atomics.
// lane l owns channels [2l, 2l+1]. Accumulates fwd/rev in registers,
// writes g_S[node] once (zeros for isolated nodes — replaces k_zero).
// ---------------------------------------------------------------------------
__global__ __launch_bounds__(256) void k_agg(
    const float* __restrict__ node_feat,
    const float* __restrict__ edge_feat,
    const float* __restrict__ edge_norm,
    const int*   __restrict__ src,
    const int*   __restrict__ is_rev)
{
    int warp = (blockIdx.x * blockDim.x + threadIdx.x) >> 5;
    int l = threadIdx.x & 31;
    if (warp >= N_NODES) return;
    int n = warp;

    int beg = g_off[n];
    int end = g_off[n + 1];

    float2 f = make_float2(0.f, 0.f);
    float2 r = make_float2(0.f, 0.f);

    for (int p = beg; p < end; p++) {
        int e  = __ldg(&g_eid[p]);          // broadcast
        int s  = __ldg(&src[e]);
        float nr = __ldg(&edge_norm[e]);
        int rv = __ldg(&is_rev[e]);
        float2 a = *reinterpret_cast<const float2*>(node_feat + (size_t)s * 64 + 2 * l);
        float2 b = *reinterpret_cast<const float2*>(edge_feat + (size_t)e * 64 + 2 * l);
        float mx = a.x * b.x * nr;
        float my = a.y * b.y * nr;
        if (rv) { r.x += mx; r.y += my; }
        else    { f.x += mx; f.y += my; }
    }

    float* o = reinterpret_cast<float*>(g_S) + (size_t)n * 128;
    *reinterpret_cast<float2*>(o + 2 * l)      = f;
    *reinterpret_cast<float2*>(o + 64 + 2 * l) = r;
}

// ---------------------------------------------------------------------------
// S5: edge_out = edge_feat @ rel_weight (64x64, fp32x2, 8x8 reg tile)
// ---------------------------------------------------------------------------
__global__ __launch_bounds__(64) void k_edge_gemm(
    const float* __restrict__ edge_feat,
    const float* __restrict__ rel_w,
    float* __restrict__ edge_out)
{
    __shared__ float Xs[64][68];
    __shared__ float Wt[64][68];

    const int t  = threadIdx.x;
    const int e0 = blockIdx.x * 64;

    #pragma unroll 8
    for (int k = 0; k < 64; k++)
        Wt[t][k] = rel_w[k * 64 + t];

    const float4* Xg = reinterpret_cast<const float4*>(edge_feat) + (size_t)e0 * 16;
    #pragma unroll
    for (int it = 0; it < 16; it++) {
        int idx = it * 64 + t;
        int rr = idx >> 4;
        int kq = idx & 15;
        float4 v = Xg[(size_t)rr * 16 + kq];
        *reinterpret_cast<float4*>(&Xs[rr][kq * 4]) = v;
    }
    __syncthreads();

    const int tx = t & 7;
    const int ty = t >> 3;
    u64 acc[8][8];
    #pragma unroll
    for (int i = 0; i < 8; i++)
        #pragma unroll
        for (int j = 0; j < 8; j++) acc[i][j] = 0ull;

    #pragma unroll 4
    for (int k4 = 0; k4 < 16; k4++) {
        ulonglong2 xv[8], wv[8];
        #pragma unroll
        for (int i = 0; i < 8; i++)
            xv[i] = *reinterpret_cast<const ulonglong2*>(&Xs[ty + 8 * i][k4 * 4]);
        #pragma unroll
        for (int j = 0; j < 8; j++)
            wv[j] = *reinterpret_cast<const ulonglong2*>(&Wt[tx + 8 * j][k4 * 4]);
        #pragma unroll
        for (int i = 0; i < 8; i++)
            #pragma unroll
            for (int j = 0; j < 8; j++)
                FMA2(acc[i][j], xv[i].x, wv[j].x);
        #pragma unroll
        for (int i = 0; i < 8; i++)
            #pragma unroll
            for (int j = 0; j < 8; j++)
                FMA2(acc[i][j], xv[i].y, wv[j].y);
    }

    #pragma unroll
    for (int i = 0; i < 8; i++) {
        float* o = edge_out + (size_t)(e0 + ty + 8 * i) * 64;
        #pragma unroll
        for (int j = 0; j < 8; j++) {
            F2U c; c.u = acc[i][j];
            o[tx + 8 * j] = c.f.x + c.f.y;
        }
    }
}

// ---------------------------------------------------------------------------
// S6: node kernel: 3-chunk K=192 GEMM, fp32x2.
// ---------------------------------------------------------------------------
__global__ __launch_bounds__(64) void k_node(
    const float* __restrict__ node_feat,
    const float* __restrict__ in_w,
    const float* __restrict__ out_w,
    const float* __restrict__ loop_w,
    const float* __restrict__ loop_rel,
    const float* __restrict__ bias,
    float* __restrict__ node_out)
{
    __shared__ float Xs[64][68];
    __shared__ float Wt[64][68];

    const int t  = threadIdx.x;
    const int r0 = blockIdx.x * 64;
    const int tx = t & 7;
    const int ty = t >> 3;
    const float* S = reinterpret_cast<const float*>(g_S);

    u64 acc[8][8];
    #pragma unroll
    for (int i = 0; i < 8; i++)
        #pragma unroll
        for (int j = 0; j < 8; j++) acc[i][j] = 0ull;

    #pragma unroll 1
    for (int ch = 0; ch < 3; ch++) {
        if (ch == 2) {
            #pragma unroll 8
            for (int k = 0; k < 64; k++)
                Wt[t][k] = loop_w[k * 64 + t] * loop_rel[k];
        } else {
            const float* W = (ch == 0) ? in_w : out_w;
            #pragma unroll 8
            for (int k = 0; k < 64; k++)
                Wt[t][k] = W[k * 64 + t];
        }

        const float* Xbase;
        size_t pitch, off;
        if (ch == 0)      { Xbase = S;         pitch = 128; off = 0;  }
        else if (ch == 1) { Xbase = S;         pitch = 128; off = 64; }
        else              { Xbase = node_feat; pitch = 64;  off = 0;  }

        #pragma unroll
        for (int it = 0; it < 16; it++) {
            int idx = it * 64 + t;
            int rr = idx >> 4;
            int kq = idx & 15;
            int gr = r0 + rr;
            float4 v = make_float4(0.f, 0.f, 0.f, 0.f);
            if (gr < N_NODES)
                v = *reinterpret_cast<const float4*>(Xbase + (size_t)gr * pitch + off + kq * 4);
            *reinterpret_cast<float4*>(&Xs[rr][kq * 4]) = v;
        }
        __syncthreads();

        #pragma unroll 4
        for (int k4 = 0; k4 < 16; k4++) {
            ulonglong2 xv[8], wv[8];
            #pragma unroll
            for (int i = 0; i < 8; i++)
                xv[i] = *reinterpret_cast<const ulonglong2*>(&Xs[ty + 8 * i][k4 * 4]);
            #pragma unroll
            for (int j = 0; j < 8; j++)
                wv[j] = *reinterpret_cast<const ulonglong2*>(&Wt[tx + 8 * j][k4 * 4]);
            #pragma unroll
            for (int i = 0; i < 8; i++)
                #pragma unroll
                for (int j = 0; j < 8; j++)
                    FMA2(acc[i][j], xv[i].x, wv[j].x);
            #pragma unroll
            for (int i = 0; i < 8; i++)
                #pragma unroll
                for (int j = 0; j < 8; j++)
                    FMA2(acc[i][j], xv[i].y, wv[j].y);
        }
        __syncthreads();
    }

    #pragma unroll
    for (int i = 0; i < 8; i++) {
        int rr = r0 + ty + 8 * i;
        if (rr < N_NODES) {
            float* o = node_out + (size_t)rr * 64;
            #pragma unroll
            for (int j = 0; j < 8; j++) {
                int c = tx + 8 * j;
                F2U cv; cv.u = acc[i][j];
                o[c] = (cv.f.x + cv.f.y) * 0.3333333f + __ldg(&bias[c]);
            }
        }
    }
}

// ---------------------------------------------------------------------------
// kernel_launch — inputs in setup_inputs dict order; is_rev is int32.
// Output: node_out [N,64] then edge_out [E,64], f32.
// ---------------------------------------------------------------------------
extern "C" void kernel_launch(void* const* d_in, const int* in_sizes, int n_in,
                              void* d_out, int out_size)
{
    const float* node_feat = (const float*)d_in[0];
    const float* edge_feat = (const float*)d_in[1];
    const float* edge_norm = (const float*)d_in[2];
    const int*   src       = (const int*)d_in[3];
    const int*   dst       = (const int*)d_in[4];
    const int*   is_rev    = (const int*)d_in[5];
    const float* in_w      = (const float*)d_in[6];
    const float* out_w     = (const float*)d_in[7];
    const float* rel_w     = (const float*)d_in[8];
    const float* loop_w    = (const float*)d_in[9];
    const float* loop_rel  = (const float*)d_in[10];
    const float* bias      = (const float*)d_in[11];

    float* out      = (float*)d_out;
    float* node_out = out;

    int write_edge = (out_size >= (N_NODES + N_EDGES) * D) ? 1 : 0;
    float* edge_out = write_edge ? (out + (size_t)N_NODES * D) : nullptr;

    // Independent edge GEMM first
    if (write_edge)
        k_edge_gemm<<<N_EDGES / 64, 64>>>(edge_feat, rel_w, edge_out);

    // CSR build (parallel 3-phase scan)
    k_init<<<(N_NODES + 255) / 256, 256>>>();
    k_hist<<<(N_EDGES + 255) / 256, 256>>>(dst);
    k_scanA<<<N_SCAN_BLKS, SCAN_BLK>>>();
    k_scanB<<<1, 512>>>();
    k_scanC<<<N_SCAN_BLKS, SCAN_BLK>>>();
    k_perm<<<(N_EDGES + 255) / 256, 256>>>(dst);

    // Gather-reduce aggregation (no fp atomics, writes g_S fully)
    k_agg<<<(N_NODES * 32 + 255) / 256, 256>>>(node_feat, edge_feat, edge_norm,
                                               src, is_rev);

    // Node GEMM + epilogue
    k_node<<<(N_NODES + 63) / 64, 64>>>(node_feat, in_w, out_w,
                                        loop_w, loop_rel, bias, node_out);
}